// round 16
// baseline (speedup 1.0000x reference)
#include <cuda_runtime.h>
#include <cuda_bf16.h>
#include <math.h>

// Problem constants (fixed by reference setup_inputs)
#define N_TOK   4096        // B*S = 2*2048
#define DIM     1024
#define NEXP    8
#define CAP     1280        // floor(2*1.25*4096/8), even
#define ECAP    (NEXP*CAP)  // 10240
#define TPC     16          // tokens per chunk (routing granularity)
#define NCHUNK  (N_TOK/TPC) // 256 chunks
#define NASSIGN (2*N_TOK)   // 8192

// Output layout (floats), concatenated in reference return order:
//  W  : [N, E, CAP],  M : [N, E, CAP],  Bt : [E, CAP, DIM],  L : [N, E]
#define OFF_W  ((size_t)0)
#define OFF_M  ((size_t)N_TOK * NEXP * CAP)     // 41,943,040 floats
#define OFF_B  (OFF_M + (size_t)N_TOK * NEXP * CAP)
#define OFF_L  (OFF_B + (size_t)NEXP * CAP * DIM)

// Fill geometry: W+M = 83,886,080 floats = 2560 spans of 32768 floats (128 KB)
#define SPAN_FLOATS 32768
#define N_SPANS     2560      // spans 0-1279 = W, 1280-2559 = M
#define M_SPAN_OFS  1280
#define BUCKET_CAP  16
#define BT_PER_BLOCK 4
#define FILL_BLOCKS (N_SPANS + ECAP / BT_PER_BLOCK)   // 5120

// Scratch (__device__ globals; no allocation allowed)
__device__ int   g_slot_token[ECAP];          // slot -> token, -1 = empty
__device__ int   g_sel [2][N_TOK];            // selected expert per (k, token)
__device__ float g_prob[2][N_TOK];            // gating prob per (k, token)
__device__ int   g_meta[2][N_TOK];            // e | (in_chunk_rank << 8)
__device__ int   g_bucket_cnt[N_SPANS];                // patches per span
__device__ int   g_bucket_idx[N_SPANS * BUCKET_CAP];   // local float index in span
__device__ float g_bucket_val[N_SPANS * BUCKET_CAP];   // value to write

// ---------------------------------------------------------------------------
// kA: one token per BLOCK (4096 blocks x 256 threads). Whole-D parallelism:
// 1 x-float4 + 8 L1-resident w-float4 per thread, warp reduce + smem reduce.
// Writes L, g_sel, g_prob only.
// ---------------------------------------------------------------------------
__global__ void kA_gate(const float4* __restrict__ X4,
                        const float4* __restrict__ G4,
                        float* __restrict__ L)
{
    __shared__ float red[8][NEXP];
    __shared__ float logits[NEXP];

    const int tid  = threadIdx.x;
    const int warp = tid >> 5;
    const int lane = tid & 31;
    const int n = blockIdx.x;

    const float4 xv = X4[(size_t)n * 256 + tid];

    float acc[NEXP];
#pragma unroll
    for (int e = 0; e < NEXP; ++e) {
        const float4 wv = G4[e * 256 + tid];
        acc[e] = xv.x * wv.x + xv.y * wv.y + xv.z * wv.z + xv.w * wv.w;
    }
#pragma unroll
    for (int e = 0; e < NEXP; ++e) {
#pragma unroll
        for (int s = 16; s > 0; s >>= 1)
            acc[e] += __shfl_xor_sync(0xffffffffu, acc[e], s);
    }
    if (lane == 0) {
#pragma unroll
        for (int e = 0; e < NEXP; ++e) red[warp][e] = acc[e];
    }
    __syncthreads();

    if (warp == 0) {
        if (lane < NEXP) {
            float s = 0.f;
#pragma unroll
            for (int w = 0; w < 8; ++w) s += red[w][lane];
            logits[lane] = s;
            L[(size_t)n * NEXP + lane] = s;
        }
        __syncwarp();
        if (lane == 0) {
            // top-1 (ties -> lowest index, matching lax.top_k)
            int i1 = 0; float v1 = logits[0];
#pragma unroll
            for (int e = 1; e < NEXP; ++e) if (logits[e] > v1) { v1 = logits[e]; i1 = e; }
            int i2 = -1; float v2 = -INFINITY;
#pragma unroll
            for (int e = 0; e < NEXP; ++e)
                if (e != i1 && logits[e] > v2) { v2 = logits[e]; i2 = e; }

            const float mx = fmaxf(v1, v2);
            const float e1 = expf(v1 - mx), e2 = expf(v2 - mx);
            const float inv = 1.f / (e1 + e2);
            g_prob[0][n] = e1 * inv;
            g_prob[1][n] = e2 * inv;
            g_sel[0][n] = i1;
            g_sel[1][n] = i2;
        }
    }
}

// ---------------------------------------------------------------------------
// kRoute (1 block, 256 thr):
//  phase 1: thread c = chunk c (16 tokens): per-chunk counts + in-chunk ranks
//  phase 2: warp-per-expert exclusive k-major prefix over chunk counts
//  phase 3: scatter slot map + per-span patch buckets
// ---------------------------------------------------------------------------
__global__ void kRoute()
{
    __shared__ int s_cnt [NCHUNK][2][NEXP];   // 16 KB
    __shared__ int s_base[NCHUNK][2][NEXP];   // 16 KB
    __shared__ int s_bcnt[N_SPANS];           // 10 KB

    const int tid  = threadIdx.x;
    const int e    = tid >> 5;           // expert (8 warps)
    const int lane = tid & 31;

    for (int i = tid; i < ECAP; i += 256)    g_slot_token[i] = -1;
    for (int i = tid; i < N_SPANS; i += 256) s_bcnt[i] = 0;

    // ---- phase 1: per-chunk counts + ranks (thread = chunk) ----
    {
        const int c = tid;               // 0..255
        const int base = c * TPC;
#pragma unroll
        for (int k = 0; k < 2; ++k) {
            int cnt[NEXP];
#pragma unroll
            for (int x = 0; x < NEXP; ++x) cnt[x] = 0;
#pragma unroll
            for (int t = 0; t < TPC; ++t) {
                const int se = g_sel[k][base + t];
                int r = 0;
#pragma unroll
                for (int x = 0; x < NEXP; ++x)
                    if (se == x) { r = cnt[x]; cnt[x] = cnt[x] + 1; }
                g_meta[k][base + t] = se | (r << 8);
            }
#pragma unroll
            for (int x = 0; x < NEXP; ++x) s_cnt[c][k][x] = cnt[x];
        }
    }
    __syncthreads();

    // ---- phase 2: exclusive k-major prefix (warp e owns expert e) ----
    int carry = 0;
    for (int k = 0; k < 2; ++k) {
        for (int c0 = 0; c0 < NCHUNK; c0 += 32) {
            const int v = s_cnt[c0 + lane][k][e];
            int inc = v;
#pragma unroll
            for (int s = 1; s < 32; s <<= 1) {
                const int t = __shfl_up_sync(0xffffffffu, inc, s);
                if (lane >= s) inc += t;
            }
            s_base[c0 + lane][k][e] = carry + (inc - v);
            carry += __shfl_sync(0xffffffffu, inc, 31);
        }
    }
    __syncthreads();

    // ---- phase 3: scatter slot map + per-span patch buckets ----
#pragma unroll 4
    for (int idx = tid; idx < NASSIGN; idx += 256) {
        const int k = idx >> 12;
        const int n = idx & (N_TOK - 1);
        const int meta = g_meta[k][n];
        const int ee = meta & 255;
        const int r  = meta >> 8;
        const int rank = s_base[n / TPC][k][ee] + r;
        if (rank < CAP) {
            const int woff = n * ECAP + ee * CAP + rank;   // < 2^26
            g_slot_token[ee * CAP + rank] = n;

            const int sp = woff >> 15;                     // /32768
            const int li = woff & (SPAN_FLOATS - 1);
            const int pW = atomicAdd(&s_bcnt[sp], 1);
            g_bucket_idx[sp * BUCKET_CAP + pW] = li;
            g_bucket_val[sp * BUCKET_CAP + pW] = g_prob[k][n];

            const int spM = sp + M_SPAN_OFS;               // same local index in M
            const int pM = atomicAdd(&s_bcnt[spM], 1);
            g_bucket_idx[spM * BUCKET_CAP + pM] = li;
            g_bucket_val[spM * BUCKET_CAP + pM] = 1.0f;
        }
    }
    __syncthreads();

    for (int i = tid; i < N_SPANS; i += 256) g_bucket_cnt[i] = s_bcnt[i];
}

// ---------------------------------------------------------------------------
// kFill: one uniform pass writing the entire W+M+Bt output (measured
// 56.8 us @ 5.94 TB/s in R14 — unchanged).
// ---------------------------------------------------------------------------
__global__ void kFill(const float4* __restrict__ X4,
                      float4* __restrict__ out4)
{
    const int tid = threadIdx.x;
    const int bid = blockIdx.x;
    const float4 z = make_float4(0.f, 0.f, 0.f, 0.f);

    if (bid < N_SPANS) {
        float4* __restrict__ P = out4 + (size_t)bid * (SPAN_FLOATS / 4);
#pragma unroll
        for (int i = 0; i < SPAN_FLOATS / 4 / 256; ++i)    // 32 stcs.128
            __stcs(P + tid + 256 * i, z);
        __syncthreads();                                    // order zero -> patch
        const int cnt = g_bucket_cnt[bid];
        if (tid < cnt) {
            ((float*)P)[g_bucket_idx[bid * BUCKET_CAP + tid]] =
                g_bucket_val[bid * BUCKET_CAP + tid];
        }
    } else {
        float4* __restrict__ B4 = out4 + (OFF_B / 4);
        const int slot0 = (bid - N_SPANS) * BT_PER_BLOCK;
#pragma unroll
        for (int j = 0; j < BT_PER_BLOCK; ++j) {
            const int slot = slot0 + j;                     // e*CAP + c
            const int t = g_slot_token[slot];               // broadcast load
            float4 o;
            if (t >= 0) o = X4[(size_t)t * 256 + tid];
            else        o = z;
            __stcs(B4 + (size_t)slot * 256 + tid, o);
        }
    }
}

// ---------------------------------------------------------------------------
extern "C" void kernel_launch(void* const* d_in, const int* in_sizes, int n_in,
                              void* d_out, int out_size)
{
    const float* x      = (const float*)d_in[0];   // [2,2048,1024]
    const float* w_gate = (const float*)d_in[1];   // [8,1024]
    float* out = (float*)d_out;
    float* L  = out + OFF_L;

    // Three kernels, one stream, no events.
    kA_gate<<<N_TOK, 256>>>((const float4*)x, (const float4*)w_gate, L);
    kRoute<<<1, 256>>>();
    kFill<<<FILL_BLOCKS, 256>>>((const float4*)x, (float4*)out);
}